// round 13
// baseline (speedup 1.0000x reference)
#include <cuda_runtime.h>
#include <cuda_bf16.h>
#include <stdint.h>

// AHardPair via mma.sync (bf16 split: hh + hl + lh).
// 64x128 CTA tiles (2 per 128x128 triangular superblock) -> 3 CTAs/SM,
// 3-buffer ring pipeline, XOR-swizzled 64B rows, fused epilogue,
// deterministic row/col partial coverage (partR + partC).

#define NPTS 8192
#define DIM  128
#define NSB  64                     // 128-wide superblock tiles per dim
#define NSBT (NSB * (NSB + 1) / 2)  // 2080 superblocks
#define SROW 64                     // row stride bytes (32 bf16), XOR swizzle
#define TILE_A (64 * SROW)          // 4096
#define TILE_B (128 * SROW)         // 8192
#define SM_AH 0
#define SM_AL TILE_A
#define SM_BH (2 * TILE_A)
#define SM_BL (2 * TILE_A + TILE_B)
#define BUF_B (2 * TILE_A + 2 * TILE_B)  // 24576
#define SMEM_TOTAL (3 * BUF_B)           // 73728 -> 3 CTAs/SM (216KB)

__device__ __nv_bfloat16 g_xh[NPTS * DIM];
__device__ __nv_bfloat16 g_xl[NPTS * DIM];
__device__ float g_sq[NPTS];
__device__ int   g_cls[NPTS];
__device__ int   g_t64min[128];
__device__ int   g_t64max[128];
__device__ float g_partR[4][64][NPTS];    // [sum][col-superblock][row]
__device__ float g_partC[4][128][NPTS];   // [sum][64-row tile][col]
__device__ float g_loss[NPTS];

// ---------------------------------------------------------- helpers ----
__device__ __forceinline__ uint32_t smem_u32(const void* p) {
    uint32_t a;
    asm("{ .reg .u64 t; cvta.to.shared.u64 t, %1; cvt.u32.u64 %0, t; }"
        : "=r"(a) : "l"(p));
    return a;
}
// swizzled byte offset of 16B chunk c (0..3) in row, 64B rows
__device__ __forceinline__ uint32_t swz(int row, int c) {
    return (uint32_t)(row * SROW + ((c ^ ((row >> 1) & 3)) << 4));
}
__device__ __forceinline__ void cpasync16(uint32_t s, const void* g) {
    asm volatile("cp.async.cg.shared.global [%0], [%1], 16;" :: "r"(s), "l"(g));
}
__device__ __forceinline__ void cpasync_commit() {
    asm volatile("cp.async.commit_group;" ::: "memory");
}
__device__ __forceinline__ void cpasync_wait1() {
    asm volatile("cp.async.wait_group 1;" ::: "memory");
}
__device__ __forceinline__ void cpasync_wait0() {
    asm volatile("cp.async.wait_group 0;" ::: "memory");
}
__device__ __forceinline__ void ldsm_x4(uint32_t* r, uint32_t addr) {
    asm volatile("ldmatrix.sync.aligned.m8n8.x4.shared.b16 {%0,%1,%2,%3}, [%4];"
                 : "=r"(r[0]), "=r"(r[1]), "=r"(r[2]), "=r"(r[3]) : "r"(addr));
}
__device__ __forceinline__ void mma_bf16(float* d, const uint32_t* a,
                                         const uint32_t* b) {
    asm volatile(
        "mma.sync.aligned.m16n8k16.row.col.f32.bf16.bf16.f32 "
        "{%0,%1,%2,%3}, {%4,%5,%6,%7}, {%8,%9}, {%0,%1,%2,%3};"
        : "+f"(d[0]), "+f"(d[1]), "+f"(d[2]), "+f"(d[3])
        : "r"(a[0]), "r"(a[1]), "r"(a[2]), "r"(a[3]), "r"(b[0]), "r"(b[1]));
}
__device__ __forceinline__ float f_sqrt(float a) {
    float r; asm("sqrt.approx.f32 %0, %1;" : "=f"(r) : "f"(a)); return r;
}
__device__ __forceinline__ float f_ex2(float a) {
    float r; asm("ex2.approx.f32 %0, %1;" : "=f"(r) : "f"(a)); return r;
}
__device__ __forceinline__ float f_rcp(float a) {
    float r; asm("rcp.approx.f32 %0, %1;" : "=f"(r) : "f"(a)); return r;
}

// ---------------------------------------------------------------- prep ----
__global__ void prep_hl(const float* __restrict__ x) {
    int i = blockIdx.x * 256 + threadIdx.x;   // over NPTS*DIM
    float v = x[i];
    __nv_bfloat16 h = __float2bfloat16_rn(v);
    g_xh[i] = h;
    g_xl[i] = __float2bfloat16_rn(v - __bfloat162float(h));
}

__global__ void prep_row(const float* __restrict__ x, const int* __restrict__ tw) {
    int i = blockIdx.x * 256 + threadIdx.x;
    if (i >= NPTS) return;
    const float4* xr = reinterpret_cast<const float4*>(x + (size_t)i * DIM);
    float s = 0.f;
#pragma unroll
    for (int q = 0; q < DIM / 4; q++) {
        float4 v = xr[q];
        s += v.x * v.x + v.y * v.y + v.z * v.z + v.w * v.w;
    }
    g_sq[i] = s;
    // targets: int64-vs-int32 wire detection (jax x64-disabled gives int32)
    bool is64 = ((tw[9] | tw[11] | tw[13] | tw[15]) == 0);
    g_cls[i] = is64 ? tw[2 * i] : tw[i];
}

__global__ void prep_tile() {   // min/max class per 64-point tile
    __shared__ int smin[64], smax[64];
    int t = blockIdx.x;
    int c = g_cls[t * 64 + threadIdx.x];
    smin[threadIdx.x] = c;
    smax[threadIdx.x] = c;
    __syncthreads();
    for (int m = 32; m; m >>= 1) {
        if (threadIdx.x < m) {
            smin[threadIdx.x] = min(smin[threadIdx.x], smin[threadIdx.x + m]);
            smax[threadIdx.x] = max(smax[threadIdx.x], smax[threadIdx.x + m]);
        }
        __syncthreads();
    }
    if (threadIdx.x == 0) { g_t64min[t] = smin[0]; g_t64max[t] = smax[0]; }
}

// ---------------------------------------------------------------- main ----
__global__ __launch_bounds__(256, 3) void pair_kernel() {
    extern __shared__ char smem[];

    // superblock decode: sbk -> (bi, bj) with bj >= bi; half picks 64 rows
    int sbk = blockIdx.x >> 1;
    const int half = blockIdx.x & 1;
    int bi = (int)((129.0f - sqrtf(16641.0f - 8.0f * (float)sbk)) * 0.5f);
    while ((bi + 1) * NSB - ((bi + 1) * bi) / 2 <= sbk) bi++;
    while (bi * NSB - (bi * (bi - 1)) / 2 > sbk) bi--;
    const int bj = bi + (sbk - (bi * NSB - (bi * (bi - 1)) / 2));
    const bool diag = (bj == bi);

    const uint32_t sb = smem_u32(smem);
    const int tid  = threadIdx.x;
    const int wid  = tid >> 5;
    const int lane = tid & 31;
    const int i0 = bi * 128 + half * 64;   // 64-row window
    const int j0 = bj * 128;               // 128-col window
    const int ti = 2 * bi + half;          // 64-row tile index

    // ---- warp tiling: 2 (M) x 4 (N) warps; warp tile 32x32 ----
    const int warp_m = wid & 1;
    const int warp_n = wid >> 1;
    const int g = lane >> 3;
    const int r = lane & 7;

    const int arow = warp_m * 32 + ((g & 1) << 3) + r;   // + mt*16
    const int ac   = (g >> 1);
    const int brow = warp_n * 32 + ((g >> 1) << 3) + r;  // + ntp*16
    const int bc   = (g & 1);

    float acc[2][4][4];
#pragma unroll
    for (int mt = 0; mt < 2; mt++)
#pragma unroll
        for (int nt = 0; nt < 4; nt++)
#pragma unroll
            for (int e = 0; e < 4; e++) acc[mt][nt][e] = 0.f;

    // ring buffer index for chunk kc is kc % 3
    auto load_chunk = [&](int kc) {
        uint32_t buf = sb + (uint32_t)((kc % 3) * BUF_B);
        {   // A: 64 rows
            int row = tid >> 2, c = tid & 3;
            uint32_t so = swz(row, c);
            size_t go = (size_t)(i0 + row) * DIM + kc * 32 + c * 8;
            cpasync16(buf + SM_AH + so, g_xh + go);
            cpasync16(buf + SM_AL + so, g_xl + go);
        }
#pragma unroll
        for (int p = 0; p < 2; p++) {   // B: 128 rows
            int q = p * 256 + tid, row = q >> 2, c = q & 3;
            uint32_t so = swz(row, c);
            size_t go = (size_t)(j0 + row) * DIM + kc * 32 + c * 8;
            cpasync16(buf + SM_BH + so, g_xh + go);
            cpasync16(buf + SM_BL + so, g_xl + go);
        }
        cpasync_commit();
    };

    load_chunk(0);
    load_chunk(1);

#pragma unroll 1
    for (int kc = 0; kc < 4; kc++) {
        if (kc < 3) cpasync_wait1(); else cpasync_wait0();
        __syncthreads();   // chunk kc resident; compute kc-1 done everywhere

        if (kc + 2 < 4) load_chunk(kc + 2);   // into freed ring slot

        const uint32_t buf = sb + (uint32_t)((kc % 3) * BUF_B);

#pragma unroll
        for (int ks = 0; ks < 2; ks++) {
            uint32_t aH[2][4], aL[2][4], bH[4][2], bL[4][2];

#pragma unroll
            for (int mt = 0; mt < 2; mt++) {
                uint32_t ao = swz(arow + mt * 16, ks * 2 + ac);
                ldsm_x4(aH[mt], buf + SM_AH + ao);
                ldsm_x4(aL[mt], buf + SM_AL + ao);
            }
#pragma unroll
            for (int ntp = 0; ntp < 2; ntp++) {
                uint32_t bo = swz(brow + ntp * 16, ks * 2 + bc);
                uint32_t t4[4];
                ldsm_x4(t4, buf + SM_BH + bo);
                bH[2 * ntp][0] = t4[0]; bH[2 * ntp][1] = t4[1];
                bH[2 * ntp + 1][0] = t4[2]; bH[2 * ntp + 1][1] = t4[3];
                ldsm_x4(t4, buf + SM_BL + bo);
                bL[2 * ntp][0] = t4[0]; bL[2 * ntp][1] = t4[1];
                bL[2 * ntp + 1][0] = t4[2]; bL[2 * ntp + 1][1] = t4[3];
            }

            // spaced same-accumulator dependencies: hh then hl then lh
#pragma unroll
            for (int mt = 0; mt < 2; mt++)
#pragma unroll
                for (int nt = 0; nt < 4; nt++) mma_bf16(acc[mt][nt], aH[mt], bH[nt]);
#pragma unroll
            for (int mt = 0; mt < 2; mt++)
#pragma unroll
                for (int nt = 0; nt < 4; nt++) mma_bf16(acc[mt][nt], aH[mt], bL[nt]);
#pragma unroll
            for (int mt = 0; mt < 2; mt++)
#pragma unroll
                for (int nt = 0; nt < 4; nt++) mma_bf16(acc[mt][nt], aL[mt], bH[nt]);
        }
    }

    // ---- fused epilogue ----
    const int lane4 = lane >> 2;
    const int lanem = lane & 3;
    const int rbase = warp_m * 32 + lane4;       // + mt*16 + h*8  (row in 64)
    const int cbase = warp_n * 32 + 2 * lanem;   // + nt*8 + p     (col in 128)

    float sqi[4], sqj[8];
    int   ci[4], cj[8];
#pragma unroll
    for (int mt = 0; mt < 2; mt++)
#pragma unroll
        for (int h = 0; h < 2; h++) {
            int gi = i0 + rbase + mt * 16 + h * 8;
            sqi[mt * 2 + h] = g_sq[gi];
            ci[mt * 2 + h]  = g_cls[gi];
        }
#pragma unroll
    for (int nt = 0; nt < 4; nt++)
#pragma unroll
        for (int p = 0; p < 2; p++) {
            int gj = j0 + cbase + nt * 8 + p;
            sqj[nt * 2 + p] = g_sq[gj];
            cj[nt * 2 + p]  = g_cls[gj];
        }

    const int jmin = min(g_t64min[2 * bj], g_t64min[2 * bj + 1]);
    const int jmax = max(g_t64max[2 * bj], g_t64max[2 * bj + 1]);
    const bool allneg = (g_t64max[ti] < jmin) || (jmax < g_t64min[ti]);

    float sR[4][4], tC[4][8];
#pragma unroll
    for (int s = 0; s < 4; s++) {
#pragma unroll
        for (int u = 0; u < 4; u++) sR[s][u] = 0.f;
#pragma unroll
        for (int u = 0; u < 8; u++) tC[s][u] = 0.f;
    }

#pragma unroll
    for (int mt = 0; mt < 2; mt++)
#pragma unroll
        for (int nt = 0; nt < 4; nt++)
#pragma unroll
            for (int e = 0; e < 4; e++) {
                int h = e >> 1, p = e & 1;
                int ui = mt * 2 + h, uj = nt * 2 + p;
                float dot = acc[mt][nt][e];
                float d2 = fmaf(-2.f, dot, sqi[ui] + sqj[uj]);
                d2 = fmaxf(d2, 1e-12f);
                float d = f_sqrt(d2);
                float uex = f_ex2(fmaf(d, -14.4269504089f, 14.4269504089f));
                float u2 = uex * uex;
                float u4 = u2 * u2;
                if (allneg) {
                    sR[1][ui] += u4; sR[3][ui] += u2;
                    tC[1][uj] += u4; tC[3][uj] += u2;
                } else {
                    int gi = i0 + rbase + mt * 16 + h * 8;
                    int gj = j0 + cbase + nt * 8 + p;
                    bool same = (ci[ui] == cj[uj]);
                    bool dg = (gi == gj);
                    if (same) {
                        if (!dg) {
                            float pi = f_rcp(u2);
                            sR[0][ui] += u4; sR[2][ui] += pi;
                            tC[0][uj] += u4; tC[2][uj] += pi;
                        }
                    } else {
                        sR[1][ui] += u4; sR[3][ui] += u2;
                        tC[1][uj] += u4; tC[3][uj] += u2;
                    }
                }
            }

    // ---- phase R: row partials -> g_partR[s][bj][i0+row] ----
    float* buf2 = reinterpret_cast<float*>(smem);    // [4][16][64] = 16KB
    __syncthreads();
    {
        int kr = warp_n * 4 + lanem;                 // 0..15
#pragma unroll
        for (int s = 0; s < 4; s++)
#pragma unroll
            for (int u = 0; u < 4; u++) {
                int row = warp_m * 32 + (u >> 1) * 16 + (u & 1) * 8 + lane4;
                buf2[(s * 16 + kr) * 64 + row] = sR[s][u];
            }
    }
    __syncthreads();
    if (tid < 64) {
#pragma unroll
        for (int s = 0; s < 4; s++) {
            float a = 0.f;
#pragma unroll
            for (int k = 0; k < 16; k++) a += buf2[(s * 16 + k) * 64 + tid];
            g_partR[s][bj][i0 + tid] = a;
        }
    }

    // ---- phase C: col partials -> g_partC[s][ti][j0+col] (non-diag sb) ----
    if (!diag) {
        __syncthreads();
        int kc2 = warp_m * 8 + lane4;                // 0..15
#pragma unroll
        for (int s = 0; s < 4; s++)
#pragma unroll
            for (int u = 0; u < 8; u++) {
                int col = warp_n * 32 + (u >> 1) * 8 + 2 * lanem + (u & 1);
                buf2[(s * 16 + kc2) * 128 + col] = tC[s][u];
            }
        __syncthreads();
        if (tid < 128) {
#pragma unroll
            for (int s = 0; s < 4; s++) {
                float a = 0.f;
#pragma unroll
                for (int k = 0; k < 16; k++) a += buf2[(s * 16 + k) * 128 + tid];
                g_partC[s][ti][j0 + tid] = a;
            }
        }
    }
}

// ------------------------------------------------------------ row loss ----
__global__ void rowloss_kernel() {
    int i = blockIdx.x * 256 + threadIdx.x;
    if (i >= NPTS) return;
    int sbk = i >> 7;   // superblock of point i
    float S1 = 0.f, S2 = 0.f, S3 = 0.f, S4 = 0.f;
    for (int b = sbk; b < 64; b++) {
        S1 += g_partR[0][b][i];
        S2 += g_partR[1][b][i];
        S3 += g_partR[2][b][i];
        S4 += g_partR[3][b][i];
    }
    for (int t = 0; t < 2 * sbk; t++) {
        S1 += g_partC[0][t][i];
        S2 += g_partC[1][t][i];
        S3 += g_partC[2][t][i];
        S4 += g_partC[3][t][i];
    }
    float alr = 1.f - S1 / (S1 + S2);
    // S3 stored scaled by e^{-4}, S4 by e^{-2}: add 4 + 2 back into the logs
    g_loss[i] = alr * (6.f + logf(S3) + logf(S4));
}

// --------------------------------------------------------- final reduce ---
__global__ void reduce_kernel(float* __restrict__ out) {
    __shared__ float sh[256];
    int tid = threadIdx.x;
    float s = 0.f;
    for (int i = tid; i < NPTS; i += 256) s += g_loss[i];
    sh[tid] = s;
    __syncthreads();
    for (int m = 128; m; m >>= 1) {
        if (tid < m) sh[tid] += sh[tid + m];
        __syncthreads();
    }
    if (tid == 0) out[0] = sh[0] / (float)NPTS;
}

// ---------------------------------------------------------------- entry ---
extern "C" void kernel_launch(void* const* d_in, const int* in_sizes, int n_in,
                              void* d_out, int out_size) {
    const float* x   = (const float*)d_in[0];
    const int*   tw  = (const int*)d_in[1];
    float*       out = (float*)d_out;

    cudaFuncSetAttribute(pair_kernel,
                         cudaFuncAttributeMaxDynamicSharedMemorySize, SMEM_TOTAL);

    prep_hl<<<NPTS * DIM / 256, 256>>>(x);
    prep_row<<<NPTS / 256, 256>>>(x, tw);
    prep_tile<<<128, 64>>>();
    pair_kernel<<<2 * NSBT, 256, SMEM_TOTAL>>>();
    rowloss_kernel<<<NPTS / 256, 256>>>();
    reduce_kernel<<<1, 256>>>(out);
}

// round 16
// speedup vs baseline: 1.1697x; 1.1697x over previous
#include <cuda_runtime.h>
#include <cuda_bf16.h>
#include <stdint.h>

// AHardPair via mma.sync (bf16 split: hh + hl + lh).
// R11 pair kernel (measured best: 108.7us) + merged prep + slim tails.

#define NPTS 8192
#define DIM  128
#define BT   128
#define NTILE (NPTS / BT)   // 64
#define NBLK (NTILE * (NTILE + 1) / 2)   // 2080
#define SROW 64             // unpadded row stride (32 bf16); XOR swizzle
#define TILE_B (128 * SROW) // 8192
#define BUF_B  (4 * TILE_B) // 32768 per chunk buffer
#define SM_AH 0
#define SM_AL TILE_B
#define SM_BH (2 * TILE_B)
#define SM_BL (3 * TILE_B)
#define SMEM_TOTAL (3 * BUF_B)   // 98304 (96 KB) -> 2 CTAs/SM

#define RL_BLOCKS 32

__device__ __nv_bfloat16 g_xh[NPTS * DIM];
__device__ __nv_bfloat16 g_xl[NPTS * DIM];
__device__ float g_sq[NPTS];
__device__ int   g_cls[NPTS];
__device__ int   g_tmin[NTILE];
__device__ int   g_tmax[NTILE];
__device__ float g_part[4][NTILE][NPTS];
__device__ float g_bsum[RL_BLOCKS];

// ---------------------------------------------------------- helpers ----
__device__ __forceinline__ uint32_t smem_u32(const void* p) {
    uint32_t a;
    asm("{ .reg .u64 t; cvta.to.shared.u64 t, %1; cvt.u32.u64 %0, t; }"
        : "=r"(a) : "l"(p));
    return a;
}
// swizzled byte offset of 16B chunk c (0..3) in row (0..127), 64B rows
__device__ __forceinline__ uint32_t swz(int row, int c) {
    return (uint32_t)(row * SROW + ((c ^ ((row >> 1) & 3)) << 4));
}
__device__ __forceinline__ void cpasync16(uint32_t s, const void* g) {
    asm volatile("cp.async.cg.shared.global [%0], [%1], 16;" :: "r"(s), "l"(g));
}
__device__ __forceinline__ void cpasync_commit() {
    asm volatile("cp.async.commit_group;" ::: "memory");
}
__device__ __forceinline__ void cpasync_wait1() {
    asm volatile("cp.async.wait_group 1;" ::: "memory");
}
__device__ __forceinline__ void cpasync_wait0() {
    asm volatile("cp.async.wait_group 0;" ::: "memory");
}
__device__ __forceinline__ void ldsm_x4(uint32_t* r, uint32_t addr) {
    asm volatile("ldmatrix.sync.aligned.m8n8.x4.shared.b16 {%0,%1,%2,%3}, [%4];"
                 : "=r"(r[0]), "=r"(r[1]), "=r"(r[2]), "=r"(r[3]) : "r"(addr));
}
__device__ __forceinline__ void mma_bf16(float* d, const uint32_t* a,
                                         const uint32_t* b) {
    asm volatile(
        "mma.sync.aligned.m16n8k16.row.col.f32.bf16.bf16.f32 "
        "{%0,%1,%2,%3}, {%4,%5,%6,%7}, {%8,%9}, {%0,%1,%2,%3};"
        : "+f"(d[0]), "+f"(d[1]), "+f"(d[2]), "+f"(d[3])
        : "r"(a[0]), "r"(a[1]), "r"(a[2]), "r"(a[3]), "r"(b[0]), "r"(b[1]));
}
__device__ __forceinline__ float f_sqrt(float a) {
    float r; asm("sqrt.approx.f32 %0, %1;" : "=f"(r) : "f"(a)); return r;
}
__device__ __forceinline__ float f_ex2(float a) {
    float r; asm("ex2.approx.f32 %0, %1;" : "=f"(r) : "f"(a)); return r;
}
__device__ __forceinline__ float f_rcp(float a) {
    float r; asm("rcp.approx.f32 %0, %1;" : "=f"(r) : "f"(a)); return r;
}

// ---------------------------------------------------------------- prep ----
// one warp per row: h/l split, row sum of squares, class
__global__ void prep_kernel(const float* __restrict__ x,
                            const int* __restrict__ tw) {
    int w    = threadIdx.x >> 5;           // warp in block (0..7)
    int lane = threadIdx.x & 31;
    int row  = blockIdx.x * 8 + w;
    const float* xr = x + (size_t)row * DIM;
    float s = 0.f;
#pragma unroll
    for (int q = 0; q < 4; q++) {
        int c = q * 32 + lane;
        float v = xr[c];
        __nv_bfloat16 h = __float2bfloat16_rn(v);
        g_xh[(size_t)row * DIM + c] = h;
        g_xl[(size_t)row * DIM + c] = __float2bfloat16_rn(v - __bfloat162float(h));
        s = fmaf(v, v, s);
    }
#pragma unroll
    for (int m = 16; m; m >>= 1) s += __shfl_xor_sync(0xffffffffu, s, m);
    if (lane == 0) {
        g_sq[row] = s;
        // targets: int64-vs-int32 wire detection (jax x64-disabled gives int32)
        bool is64 = ((tw[9] | tw[11] | tw[13] | tw[15]) == 0);
        g_cls[row] = is64 ? tw[2 * row] : tw[row];
    }
}

__global__ void prep_tile() {
    __shared__ int smin[128], smax[128];
    int t = blockIdx.x;
    int c = g_cls[t * BT + threadIdx.x];
    smin[threadIdx.x] = c;
    smax[threadIdx.x] = c;
    __syncthreads();
    for (int m = 64; m; m >>= 1) {
        if (threadIdx.x < m) {
            smin[threadIdx.x] = min(smin[threadIdx.x], smin[threadIdx.x + m]);
            smax[threadIdx.x] = max(smax[threadIdx.x], smax[threadIdx.x + m]);
        }
        __syncthreads();
    }
    if (threadIdx.x == 0) { g_tmin[t] = smin[0]; g_tmax[t] = smax[0]; }
}

// ---------------------------------------------------------------- main ----
__global__ __launch_bounds__(256, 2) void pair_kernel() {
    extern __shared__ char smem[];

    // triangular decode: block b -> (bi, bj), bj >= bi
    int b = blockIdx.x;
    int bi = (int)((129.0f - sqrtf(16641.0f - 8.0f * (float)b)) * 0.5f);
    while ((bi + 1) * NTILE - ((bi + 1) * bi) / 2 <= b) bi++;
    while (bi * NTILE - (bi * (bi - 1)) / 2 > b) bi--;
    const int bj = bi + (b - (bi * NTILE - (bi * (bi - 1)) / 2));
    const bool offdiag = (bj != bi);

    const uint32_t sb = smem_u32(smem);
    const int tid  = threadIdx.x;
    const int wid  = tid >> 5;
    const int lane = tid & 31;
    const int i0 = bi * BT;
    const int j0 = bj * BT;

    // ---- warp tiling: 2 (M) x 4 (N) warps; warp tile 64x32 ----
    const int warp_m = wid & 1;
    const int warp_n = wid >> 1;
    const int g  = lane >> 3;
    const int r  = lane & 7;

    const int arow = warp_m * 64 + ((g & 1) << 3) + r;   // + mt*16
    const int ac   = (g >> 1);                           // chunk lo/hi (+ks*2)
    const int brow = warp_n * 32 + ((g >> 1) << 3) + r;  // + ntp*16
    const int bc   = (g & 1);
    const uint32_t boffd = offdiag ? (uint32_t)SM_BH : (uint32_t)SM_AH;

    float acc[4][4][4];
#pragma unroll
    for (int mt = 0; mt < 4; mt++)
#pragma unroll
        for (int nt = 0; nt < 4; nt++)
#pragma unroll
            for (int e = 0; e < 4; e++) acc[mt][nt][e] = 0.f;

    // ring buffer index for chunk kc is kc % 3
    auto load_chunk = [&](int kc) {
        uint32_t buf = sb + (uint32_t)((kc % 3) * BUF_B);
#pragma unroll
        for (int p = 0; p < 2; p++) {
            int q = p * 256 + tid, row = q >> 2, c = q & 3;
            uint32_t so = swz(row, c);
            size_t go = (size_t)(i0 + row) * DIM + kc * 32 + c * 8;
            cpasync16(buf + SM_AH + so, g_xh + go);
            cpasync16(buf + SM_AL + so, g_xl + go);
            if (offdiag) {
                size_t gob = (size_t)(j0 + row) * DIM + kc * 32 + c * 8;
                cpasync16(buf + SM_BH + so, g_xh + gob);
                cpasync16(buf + SM_BL + so, g_xl + gob);
            }
        }
        cpasync_commit();
    };

    load_chunk(0);
    load_chunk(1);

#pragma unroll 1
    for (int kc = 0; kc < 4; kc++) {
        if (kc < 3) cpasync_wait1(); else cpasync_wait0();
        __syncthreads();   // chunk kc resident; compute kc-1 complete everywhere

        // prefetch kc+2 into buf (kc+2)%3 == (kc-1)%3, freed by the sync above
        if (kc + 2 < 4) load_chunk(kc + 2);

        const uint32_t buf = sb + (uint32_t)((kc % 3) * BUF_B);
        const uint32_t abuf = buf + SM_AH;
        const uint32_t albuf = buf + SM_AL;
        const uint32_t bhb = buf + boffd;
        const uint32_t blb = bhb + TILE_B;

#pragma unroll
        for (int ks = 0; ks < 2; ks++) {
            uint32_t aH[4][4], aL[4][4], bH[4][2], bL[4][2];

#pragma unroll
            for (int mt = 0; mt < 4; mt++) {
                uint32_t ao = swz(arow + mt * 16, ks * 2 + ac);
                ldsm_x4(aH[mt], abuf + ao);
                ldsm_x4(aL[mt], albuf + ao);
            }
#pragma unroll
            for (int ntp = 0; ntp < 2; ntp++) {
                uint32_t bo = swz(brow + ntp * 16, ks * 2 + bc);
                uint32_t t4[4];
                ldsm_x4(t4, bhb + bo);
                bH[2 * ntp][0] = t4[0]; bH[2 * ntp][1] = t4[1];
                bH[2 * ntp + 1][0] = t4[2]; bH[2 * ntp + 1][1] = t4[3];
                ldsm_x4(t4, blb + bo);
                bL[2 * ntp][0] = t4[0]; bL[2 * ntp][1] = t4[1];
                bL[2 * ntp + 1][0] = t4[2]; bL[2 * ntp + 1][1] = t4[3];
            }

            // spaced same-accumulator dependencies: hh then hl then lh
#pragma unroll
            for (int mt = 0; mt < 4; mt++)
#pragma unroll
                for (int nt = 0; nt < 4; nt++) mma_bf16(acc[mt][nt], aH[mt], bH[nt]);
#pragma unroll
            for (int mt = 0; mt < 4; mt++)
#pragma unroll
                for (int nt = 0; nt < 4; nt++) mma_bf16(acc[mt][nt], aH[mt], bL[nt]);
#pragma unroll
            for (int mt = 0; mt < 4; mt++)
#pragma unroll
                for (int nt = 0; nt < 4; nt++) mma_bf16(acc[mt][nt], aL[mt], bH[nt]);
        }
    }

    // ---- fused epilogue ----
    const int lane4 = lane >> 2;
    const int lanem = lane & 3;
    const int rbase = warp_m * 64 + lane4;
    const int cbase = warp_n * 32 + 2 * lanem;

    float sqi[8], sqj[8];
    int   ci[8], cj[8];
#pragma unroll
    for (int mt = 0; mt < 4; mt++)
#pragma unroll
        for (int h = 0; h < 2; h++) {
            int gi = i0 + rbase + mt * 16 + h * 8;
            sqi[mt * 2 + h] = g_sq[gi];
            ci[mt * 2 + h]  = g_cls[gi];
        }
#pragma unroll
    for (int nt = 0; nt < 4; nt++)
#pragma unroll
        for (int p = 0; p < 2; p++) {
            int gj = j0 + cbase + nt * 8 + p;
            sqj[nt * 2 + p] = g_sq[gj];
            cj[nt * 2 + p]  = g_cls[gj];
        }

    const bool allneg = (g_tmax[bi] < g_tmin[bj]) || (g_tmax[bj] < g_tmin[bi]);

    float sR[4][8], tC[4][8];
#pragma unroll
    for (int s = 0; s < 4; s++)
#pragma unroll
        for (int u = 0; u < 8; u++) { sR[s][u] = 0.f; tC[s][u] = 0.f; }

#pragma unroll
    for (int mt = 0; mt < 4; mt++)
#pragma unroll
        for (int nt = 0; nt < 4; nt++)
#pragma unroll
            for (int e = 0; e < 4; e++) {
                int h = e >> 1, p = e & 1;
                int ui = mt * 2 + h, uj = nt * 2 + p;
                float dot = acc[mt][nt][e];
                float d2 = fmaf(-2.f, dot, sqi[ui] + sqj[uj]);
                d2 = fmaxf(d2, 1e-12f);
                float d = f_sqrt(d2);
                float uex = f_ex2(fmaf(d, -14.4269504089f, 14.4269504089f));
                float u2 = uex * uex;
                float u4 = u2 * u2;
                if (allneg) {
                    sR[1][ui] += u4; sR[3][ui] += u2;
                    tC[1][uj] += u4; tC[3][uj] += u2;
                } else {
                    int gi = i0 + rbase + mt * 16 + h * 8;
                    int gj = j0 + cbase + nt * 8 + p;
                    bool same = (ci[ui] == cj[uj]);
                    bool diag = (gi == gj);
                    if (same) {
                        if (!diag) {
                            float pi = f_rcp(u2);
                            sR[0][ui] += u4; sR[2][ui] += pi;
                            tC[0][uj] += u4; tC[2][uj] += pi;
                        }
                    } else {
                        sR[1][ui] += u4; sR[3][ui] += u2;
                        tC[1][uj] += u4; tC[3][uj] += u2;
                    }
                }
            }

    // ---- phase R: row partials -> g_part[s][bj][i0+row] ----
    float* buf2 = reinterpret_cast<float*>(smem);    // [4][16][128] = 32KB
    __syncthreads();
    {
        int kr = warp_n * 4 + lanem;
#pragma unroll
        for (int s = 0; s < 4; s++)
#pragma unroll
            for (int u = 0; u < 8; u++) {
                int row = warp_m * 64 + (u >> 1) * 16 + (u & 1) * 8 + lane4;
                buf2[(s * 16 + kr) * 128 + row] = sR[s][u];
            }
    }
    __syncthreads();
    if (tid < 128) {
#pragma unroll
        for (int s = 0; s < 4; s++) {
            float a = 0.f;
#pragma unroll
            for (int k = 0; k < 16; k++) a += buf2[(s * 16 + k) * 128 + tid];
            g_part[s][bj][i0 + tid] = a;
        }
    }

    // ---- phase C: col partials -> g_part[s][bi][j0+col] (offdiag) ----
    if (offdiag) {
        __syncthreads();
        int kc2 = warp_m * 8 + lane4;
#pragma unroll
        for (int s = 0; s < 4; s++)
#pragma unroll
            for (int u = 0; u < 8; u++) {
                int col = warp_n * 32 + (u >> 1) * 8 + 2 * lanem + (u & 1);
                buf2[(s * 16 + kc2) * 128 + col] = tC[s][u];
            }
        __syncthreads();
        if (tid < 128) {
#pragma unroll
            for (int s = 0; s < 4; s++) {
                float a = 0.f;
#pragma unroll
                for (int k = 0; k < 16; k++) a += buf2[(s * 16 + k) * 128 + tid];
                g_part[s][bi][j0 + tid] = a;
            }
        }
    }
}

// ---------------------------------------- row loss + per-block sums ----
__global__ void rowloss_kernel() {
    __shared__ float sh[256];
    int i = blockIdx.x * 256 + threadIdx.x;
    float S1 = 0.f, S2 = 0.f, S3 = 0.f, S4 = 0.f;
#pragma unroll 8
    for (int b = 0; b < NTILE; b++) {
        S1 += g_part[0][b][i];
        S2 += g_part[1][b][i];
        S3 += g_part[2][b][i];
        S4 += g_part[3][b][i];
    }
    float alr = 1.f - S1 / (S1 + S2);
    // S3 stored scaled by e^{-4}, S4 by e^{-2}: add 4 + 2 back into the logs
    float loss = alr * (6.f + logf(S3) + logf(S4));
    sh[threadIdx.x] = loss;
    __syncthreads();
    for (int m = 128; m; m >>= 1) {
        if (threadIdx.x < m) sh[threadIdx.x] += sh[threadIdx.x + m];
        __syncthreads();
    }
    if (threadIdx.x == 0) g_bsum[blockIdx.x] = sh[0];
}

// --------------------------------------------------------- final reduce ---
__global__ void reduce_kernel(float* __restrict__ out) {
    int tid = threadIdx.x;   // 32 threads
    float s = (tid < RL_BLOCKS) ? g_bsum[tid] : 0.f;
#pragma unroll
    for (int m = 16; m; m >>= 1) s += __shfl_xor_sync(0xffffffffu, s, m);
    if (tid == 0) out[0] = s / (float)NPTS;
}

// ---------------------------------------------------------------- entry ---
extern "C" void kernel_launch(void* const* d_in, const int* in_sizes, int n_in,
                              void* d_out, int out_size) {
    const float* x   = (const float*)d_in[0];
    const int*   tw  = (const int*)d_in[1];
    float*       out = (float*)d_out;

    cudaFuncSetAttribute(pair_kernel,
                         cudaFuncAttributeMaxDynamicSharedMemorySize, SMEM_TOTAL);

    prep_kernel<<<NPTS / 8, 256>>>(x, tw);
    prep_tile<<<NTILE, 128>>>();
    pair_kernel<<<NBLK, 256, SMEM_TOTAL>>>();
    rowloss_kernel<<<RL_BLOCKS, 256>>>();   // NPTS / 256 == RL_BLOCKS
    reduce_kernel<<<1, 32>>>(out);
}